// round 1
// baseline (speedup 1.0000x reference)
#include <cuda_runtime.h>
#include <math.h>

// ---------------------------------------------------------------------------
// MoE expert-choice: route -> top-512/expert -> gather -> GEMM1+SiLU -> GEMM2
//                    -> gated scatter-add.
// Shapes: x[4,2048,1024] f32, choice[8,1024], w1[8,4096,1024], w2[8,1024,4096]
// out[4,2048,1024] f32.
// ---------------------------------------------------------------------------

#define NE     8
#define DM     1024
#define DF     4096
#define SEQ    2048
#define BATCH  4
#define TOPK   512
#define NPAIR  (BATCH * NE)   // 32

// Scratch (static device arrays; allocation APIs are forbidden).
__device__ float g_moe_probs[BATCH * SEQ * NE];            // softmax probs
__device__ int   g_moe_idx[NPAIR * TOPK];                  // selected token ids
__device__ float g_moe_gate[NPAIR * TOPK];                 // gates
__device__ float g_moe_h[(size_t)NPAIR * TOPK * DF];       // GEMM1 output (268MB)

// ---------------------------------------------------------------------------
// 1) Routing: logits = x . choice^T, softmax over experts. One block / token.
// ---------------------------------------------------------------------------
__global__ void k_route(const float* __restrict__ x,
                        const float* __restrict__ choice) {
    const int token = blockIdx.x;                 // 0 .. BATCH*SEQ-1
    const float* xr = x + (size_t)token * DM;
    const int t = threadIdx.x;                    // 128 threads

    float acc[NE];
#pragma unroll
    for (int e = 0; e < NE; e++) acc[e] = 0.f;

    for (int d = t; d < DM; d += 128) {
        const float xv = xr[d];
#pragma unroll
        for (int e = 0; e < NE; e++)
            acc[e] = fmaf(xv, choice[e * DM + d], acc[e]);
    }

    __shared__ float red[NE][128];
#pragma unroll
    for (int e = 0; e < NE; e++) red[e][t] = acc[e];
    __syncthreads();

    for (int ofs = 64; ofs > 0; ofs >>= 1) {
        if (t < ofs) {
#pragma unroll
            for (int e = 0; e < NE; e++) red[e][t] += red[e][t + ofs];
        }
        __syncthreads();
    }

    if (t == 0) {
        float l[NE], mx = -1e30f;
#pragma unroll
        for (int e = 0; e < NE; e++) { l[e] = red[e][0]; mx = fmaxf(mx, l[e]); }
        float s = 0.f;
#pragma unroll
        for (int e = 0; e < NE; e++) { l[e] = expf(l[e] - mx); s += l[e]; }
        const float inv = 1.f / s;
#pragma unroll
        for (int e = 0; e < NE; e++) g_moe_probs[token * NE + e] = l[e] * inv;
    }
}

// ---------------------------------------------------------------------------
// 2) Top-K per (batch, expert): exact threshold via binary search on ordered
//    float bits. Output set/gates; slot order is irrelevant to the final sum.
// ---------------------------------------------------------------------------
__global__ void k_topk() {
    const int pair = blockIdx.x;                  // b*NE + e
    const int b = pair >> 3, e = pair & 7;
    const int t = threadIdx.x;                    // 1024 threads

    __shared__ unsigned keys[SEQ];
    __shared__ int s_cnt;

    for (int s = t; s < SEQ; s += blockDim.x) {
        unsigned bits = __float_as_uint(g_moe_probs[((size_t)b * SEQ + s) * NE + e]);
        keys[s] = (bits & 0x80000000u) ? ~bits : (bits | 0x80000000u);
    }
    __syncthreads();

    // Largest T with count(key >= T) >= TOPK.
    unsigned lo = 0u, hi = 0xFFFFFFFFu;
    while (lo < hi) {
        const unsigned mid = lo + ((hi - lo) >> 1) + 1u;  // in (lo, hi]
        if (t == 0) s_cnt = 0;
        __syncthreads();
        int c = 0;
        for (int s = t; s < SEQ; s += blockDim.x) c += (keys[s] >= mid);
#pragma unroll
        for (int o = 16; o > 0; o >>= 1) c += __shfl_down_sync(0xffffffffu, c, o);
        if ((t & 31) == 0 && c) atomicAdd(&s_cnt, c);
        __syncthreads();
        const int cnt = s_cnt;
        __syncthreads();                          // read-before-next-reset
        if (cnt >= TOPK) lo = mid; else hi = mid - 1u;
    }
    const unsigned T = lo;

    if (t == 0) s_cnt = 0;
    __syncthreads();
    for (int s = t; s < SEQ; s += blockDim.x) {
        if (keys[s] > T) {
            const int p = atomicAdd(&s_cnt, 1);
            g_moe_idx[pair * TOPK + p]  = s;
            g_moe_gate[pair * TOPK + p] = g_moe_probs[((size_t)b * SEQ + s) * NE + e];
        }
    }
    __syncthreads();
    for (int s = t; s < SEQ; s += blockDim.x) {
        if (keys[s] == T) {
            const int p = atomicAdd(&s_cnt, 1);
            if (p < TOPK) {
                g_moe_idx[pair * TOPK + p]  = s;
                g_moe_gate[pair * TOPK + p] = g_moe_probs[((size_t)b * SEQ + s) * NE + e];
            }
        }
    }
}

// ---------------------------------------------------------------------------
// 3) GEMM1 (gathered A) + SiLU: h[p,m,n] = silu( sum_d x[b,I[p,m],d]*w1[e,n,d] )
//    Tiles: 128x128x8, 256 threads, 8x8 per thread, double-buffered smem.
// ---------------------------------------------------------------------------
__global__ void __launch_bounds__(256, 2) k_gemm1(const float* __restrict__ x,
                                                  const float* __restrict__ w1) {
    const int pair  = blockIdx.z;
    const int b     = pair >> 3, e = pair & 7;
    const int mBase = blockIdx.y * 128;
    const int nBase = blockIdx.x * 128;

    const float* A = x  + (size_t)b * SEQ * DM;
    const float* B = w1 + (size_t)e * DF * DM + (size_t)nBase * DM;
    float* C = g_moe_h + (size_t)pair * TOPK * DF + (size_t)mBase * DF + nBase;

    __shared__ float As[2][8][132];
    __shared__ float Bs[2][8][132];
    __shared__ int rowIdx[128];

    const int tid = threadIdx.x;
    if (tid < 128) rowIdx[tid] = g_moe_idx[pair * TOPK + mBase + tid];
    __syncthreads();

    const int tx = tid & 15, ty = tid >> 4;
    const int lr = tid >> 1;                      // 0..127 tile row
    const int lc = (tid & 1) * 4;                 // 0 or 4

    const float* aRow = A + (size_t)rowIdx[lr] * DM + lc;
    const float* bRow = B + (size_t)lr * DM + lc;

    float acc[8][8];
#pragma unroll
    for (int i = 0; i < 8; i++)
#pragma unroll
        for (int j = 0; j < 8; j++) acc[i][j] = 0.f;

    float4 a4 = *(const float4*)(aRow);
    float4 b4 = *(const float4*)(bRow);
    As[0][lc + 0][lr] = a4.x; As[0][lc + 1][lr] = a4.y;
    As[0][lc + 2][lr] = a4.z; As[0][lc + 3][lr] = a4.w;
    Bs[0][lc + 0][lr] = b4.x; Bs[0][lc + 1][lr] = b4.y;
    Bs[0][lc + 2][lr] = b4.z; Bs[0][lc + 3][lr] = b4.w;
    __syncthreads();

    const int KT = DM / 8;                        // 128
#pragma unroll 1
    for (int kt = 0; kt < KT; ++kt) {
        const int cur = kt & 1, nxt = cur ^ 1;
        if (kt + 1 < KT) {
            a4 = *(const float4*)(aRow + (kt + 1) * 8);
            b4 = *(const float4*)(bRow + (kt + 1) * 8);
        }
#pragma unroll
        for (int k = 0; k < 8; ++k) {
            float a[8], bb[8];
#pragma unroll
            for (int i = 0; i < 8; i++) a[i]  = As[cur][k][ty * 8 + i];
#pragma unroll
            for (int j = 0; j < 8; j++) bb[j] = Bs[cur][k][tx * 8 + j];
#pragma unroll
            for (int i = 0; i < 8; i++)
#pragma unroll
                for (int j = 0; j < 8; j++)
                    acc[i][j] = fmaf(a[i], bb[j], acc[i][j]);
        }
        if (kt + 1 < KT) {
            As[nxt][lc + 0][lr] = a4.x; As[nxt][lc + 1][lr] = a4.y;
            As[nxt][lc + 2][lr] = a4.z; As[nxt][lc + 3][lr] = a4.w;
            Bs[nxt][lc + 0][lr] = b4.x; Bs[nxt][lc + 1][lr] = b4.y;
            Bs[nxt][lc + 2][lr] = b4.z; Bs[nxt][lc + 3][lr] = b4.w;
        }
        __syncthreads();
    }

#pragma unroll
    for (int i = 0; i < 8; i++) {
        float* crow = C + (size_t)(ty * 8 + i) * DF + tx * 8;
#pragma unroll
        for (int j = 0; j < 8; j++) {
            const float v = acc[i][j];
            crow[j] = v / (1.f + expf(-v));       // silu
        }
    }
}

// ---------------------------------------------------------------------------
// 4) GEMM2 + gated scatter: out[b,I[p,m],d] += G[p,m] * sum_o h[p,m,o]*w2[e,d,o]
// ---------------------------------------------------------------------------
__global__ void __launch_bounds__(256, 2) k_gemm2(const float* __restrict__ w2,
                                                  float* __restrict__ out) {
    const int pair  = blockIdx.z;
    const int b     = pair >> 3, e = pair & 7;
    const int mBase = blockIdx.y * 128;
    const int nBase = blockIdx.x * 128;

    const float* A = g_moe_h + (size_t)pair * TOPK * DF + (size_t)mBase * DF;
    const float* B = w2 + (size_t)e * DM * DF + (size_t)nBase * DF;

    __shared__ float As[2][8][132];
    __shared__ float Bs[2][8][132];
    __shared__ int   rowIdx[128];
    __shared__ float rowGate[128];

    const int tid = threadIdx.x;
    if (tid < 128) {
        rowIdx[tid]  = g_moe_idx[pair * TOPK + mBase + tid];
        rowGate[tid] = g_moe_gate[pair * TOPK + mBase + tid];
    }

    const int tx = tid & 15, ty = tid >> 4;
    const int lr = tid >> 1;
    const int lc = (tid & 1) * 4;

    const float* aRow = A + (size_t)lr * DF + lc;
    const float* bRow = B + (size_t)lr * DF + lc;

    float acc[8][8];
#pragma unroll
    for (int i = 0; i < 8; i++)
#pragma unroll
        for (int j = 0; j < 8; j++) acc[i][j] = 0.f;

    float4 a4 = *(const float4*)(aRow);
    float4 b4 = *(const float4*)(bRow);
    As[0][lc + 0][lr] = a4.x; As[0][lc + 1][lr] = a4.y;
    As[0][lc + 2][lr] = a4.z; As[0][lc + 3][lr] = a4.w;
    Bs[0][lc + 0][lr] = b4.x; Bs[0][lc + 1][lr] = b4.y;
    Bs[0][lc + 2][lr] = b4.z; Bs[0][lc + 3][lr] = b4.w;
    __syncthreads();

    const int KT = DF / 8;                        // 512
#pragma unroll 1
    for (int kt = 0; kt < KT; ++kt) {
        const int cur = kt & 1, nxt = cur ^ 1;
        if (kt + 1 < KT) {
            a4 = *(const float4*)(aRow + (kt + 1) * 8);
            b4 = *(const float4*)(bRow + (kt + 1) * 8);
        }
#pragma unroll
        for (int k = 0; k < 8; ++k) {
            float a[8], bb[8];
#pragma unroll
            for (int i = 0; i < 8; i++) a[i]  = As[cur][k][ty * 8 + i];
#pragma unroll
            for (int j = 0; j < 8; j++) bb[j] = Bs[cur][k][tx * 8 + j];
#pragma unroll
            for (int i = 0; i < 8; i++)
#pragma unroll
                for (int j = 0; j < 8; j++)
                    acc[i][j] = fmaf(a[i], bb[j], acc[i][j]);
        }
        if (kt + 1 < KT) {
            As[nxt][lc + 0][lr] = a4.x; As[nxt][lc + 1][lr] = a4.y;
            As[nxt][lc + 2][lr] = a4.z; As[nxt][lc + 3][lr] = a4.w;
            Bs[nxt][lc + 0][lr] = b4.x; Bs[nxt][lc + 1][lr] = b4.y;
            Bs[nxt][lc + 2][lr] = b4.z; Bs[nxt][lc + 3][lr] = b4.w;
        }
        __syncthreads();
    }

    float* outB = out + (size_t)b * SEQ * DM;
#pragma unroll
    for (int i = 0; i < 8; i++) {
        const int m   = ty * 8 + i;
        const int tok = rowIdx[m];
        const float g = rowGate[m];
        float* orow = outB + (size_t)tok * DM + nBase + tx * 8;
#pragma unroll
        for (int j = 0; j < 8; j++)
            atomicAdd(&orow[j], g * acc[i][j]);
    }
}

// ---------------------------------------------------------------------------
// 5) Zero the output (it is poisoned before timing).
// ---------------------------------------------------------------------------
__global__ void k_zero(float* __restrict__ out, int n4) {
    const int i = blockIdx.x * blockDim.x + threadIdx.x;
    if (i < n4) ((float4*)out)[i] = make_float4(0.f, 0.f, 0.f, 0.f);
}

// ---------------------------------------------------------------------------
extern "C" void kernel_launch(void* const* d_in, const int* in_sizes, int n_in,
                              void* d_out, int out_size) {
    const float* x      = (const float*)d_in[0];
    const float* choice = (const float*)d_in[1];
    const float* w1     = (const float*)d_in[2];
    const float* w2     = (const float*)d_in[3];
    float* out = (float*)d_out;

    k_route<<<BATCH * SEQ, 128>>>(x, choice);
    k_topk<<<NPAIR, 1024>>>();
    k_gemm1<<<dim3(DF / 128, TOPK / 128, NPAIR), 256>>>(x, w1);
    const int n4 = BATCH * SEQ * DM / 4;
    k_zero<<<(n4 + 255) / 256, 256>>>(out, n4);
    k_gemm2<<<dim3(DM / 128, TOPK / 128, NPAIR), 256>>>(w2, out);
}

// round 3
// speedup vs baseline: 3.5642x; 3.5642x over previous
#include <cuda_runtime.h>
#include <cstdint>
#include <math.h>

// ---------------------------------------------------------------------------
// MoE expert-choice via mma.sync tf32 (sm_103 ptxas target lacks tcgen05).
// route -> top-512/expert -> gather(tf32 RN) -> GEMM1+SiLU -> GEMM2 -> scatter
// ---------------------------------------------------------------------------

#define NE     8
#define DM     1024
#define DF     4096
#define SEQ    2048
#define BATCH  4
#define TOPK   512
#define NPAIR  32

__device__ float g_probs[BATCH * SEQ * NE];
__device__ int   g_idx[NPAIR * TOPK];
__device__ float g_gate[NPAIR * TOPK];
__device__ __align__(128) float g_xg[(size_t)NPAIR * TOPK * DM];    //  64MB
__device__ __align__(128) float g_h [(size_t)NPAIR * TOPK * DF];    // 256MB
__device__ __align__(128) float g_w1r[(size_t)NE * DF * DM];        // 128MB
__device__ __align__(128) float g_w2r[(size_t)NE * DM * DF];        // 128MB

__device__ __forceinline__ float tf32r(float x) {   // RN round to tf32
    uint32_t u;
    asm("cvt.rna.tf32.f32 %0, %1;" : "=r"(u) : "f"(x));
    return __uint_as_float(u);
}

#define CP16(dst, src)  asm volatile("cp.async.cg.shared.global [%0], [%1], 16;" :: "r"(dst), "l"(src))
#define CP_COMMIT()     asm volatile("cp.async.commit_group;" ::: "memory")

__device__ __forceinline__ uint32_t smem_u32(const void* p) {
    uint32_t a;
    asm("{ .reg .u64 t; cvta.to.shared.u64 t, %1; cvt.u32.u64 %0, t; }" : "=r"(a) : "l"(p));
    return a;
}

__device__ __forceinline__ void mma_tf32(float* c, const uint32_t* a, const uint32_t* b) {
    asm volatile(
        "mma.sync.aligned.m16n8k8.row.col.f32.tf32.tf32.f32 "
        "{%0,%1,%2,%3}, {%4,%5,%6,%7}, {%8,%9}, {%0,%1,%2,%3};"
        : "+f"(c[0]), "+f"(c[1]), "+f"(c[2]), "+f"(c[3])
        : "r"(a[0]), "r"(a[1]), "r"(a[2]), "r"(a[3]), "r"(b[0]), "r"(b[1]));
}

// ---------------------------------------------------------------------------
// 1) Routing softmax (fp32 exact)
// ---------------------------------------------------------------------------
__global__ void k_route(const float* __restrict__ x, const float* __restrict__ choice) {
    const int token = blockIdx.x;
    const float* xr = x + (size_t)token * DM;
    const int t = threadIdx.x;               // 128

    float acc[NE];
#pragma unroll
    for (int e = 0; e < NE; e++) acc[e] = 0.f;
    for (int d = t; d < DM; d += 128) {
        const float xv = xr[d];
#pragma unroll
        for (int e = 0; e < NE; e++) acc[e] = fmaf(xv, choice[e * DM + d], acc[e]);
    }
    __shared__ float red[NE][128];
#pragma unroll
    for (int e = 0; e < NE; e++) red[e][t] = acc[e];
    __syncthreads();
    for (int ofs = 64; ofs > 0; ofs >>= 1) {
        if (t < ofs) {
#pragma unroll
            for (int e = 0; e < NE; e++) red[e][t] += red[e][t + ofs];
        }
        __syncthreads();
    }
    if (t == 0) {
        float l[NE], mx = -1e30f;
#pragma unroll
        for (int e = 0; e < NE; e++) { l[e] = red[e][0]; mx = fmaxf(mx, l[e]); }
        float s = 0.f;
#pragma unroll
        for (int e = 0; e < NE; e++) { l[e] = expf(l[e] - mx); s += l[e]; }
        const float inv = 1.f / s;
#pragma unroll
        for (int e = 0; e < NE; e++) g_probs[token * NE + e] = l[e] * inv;
    }
}

// ---------------------------------------------------------------------------
// 2) Exact top-K per (batch, expert)
// ---------------------------------------------------------------------------
__global__ void k_topk() {
    const int pair = blockIdx.x, b = pair >> 3, e = pair & 7;
    const int t = threadIdx.x;               // 1024
    __shared__ unsigned keys[SEQ];
    __shared__ int s_cnt;

    for (int s = t; s < SEQ; s += blockDim.x) {
        unsigned bits = __float_as_uint(g_probs[((size_t)b * SEQ + s) * NE + e]);
        keys[s] = (bits & 0x80000000u) ? ~bits : (bits | 0x80000000u);
    }
    __syncthreads();

    unsigned lo = 0u, hi = 0xFFFFFFFFu;
    while (lo < hi) {
        const unsigned mid = lo + ((hi - lo) >> 1) + 1u;
        if (t == 0) s_cnt = 0;
        __syncthreads();
        int c = 0;
        for (int s = t; s < SEQ; s += blockDim.x) c += (keys[s] >= mid);
#pragma unroll
        for (int o = 16; o > 0; o >>= 1) c += __shfl_down_sync(0xffffffffu, c, o);
        if ((t & 31) == 0 && c) atomicAdd(&s_cnt, c);
        __syncthreads();
        const int cnt = s_cnt;
        __syncthreads();
        if (cnt >= TOPK) lo = mid; else hi = mid - 1u;
    }
    const unsigned T = lo;

    if (t == 0) s_cnt = 0;
    __syncthreads();
    for (int s = t; s < SEQ; s += blockDim.x) {
        if (keys[s] > T) {
            const int p = atomicAdd(&s_cnt, 1);
            g_idx[pair * TOPK + p]  = s;
            g_gate[pair * TOPK + p] = g_probs[((size_t)b * SEQ + s) * NE + e];
        }
    }
    __syncthreads();
    for (int s = t; s < SEQ; s += blockDim.x) {
        if (keys[s] == T) {
            const int p = atomicAdd(&s_cnt, 1);
            if (p < TOPK) {
                g_idx[pair * TOPK + p]  = s;
                g_gate[pair * TOPK + p] = g_probs[((size_t)b * SEQ + s) * NE + e];
            }
        }
    }
}

// ---------------------------------------------------------------------------
// 3) Weight prep: RN-round to tf32
// ---------------------------------------------------------------------------
__global__ void k_prep(const float* __restrict__ w1, const float* __restrict__ w2) {
    const size_t i = (size_t)blockIdx.x * blockDim.x + threadIdx.x;
    const size_t N4 = (size_t)NE * DF * DM / 4;
    if (i >= N4) return;
    float4 a = ((const float4*)w1)[i];
    a.x = tf32r(a.x); a.y = tf32r(a.y); a.z = tf32r(a.z); a.w = tf32r(a.w);
    ((float4*)g_w1r)[i] = a;
    float4 c = ((const float4*)w2)[i];
    c.x = tf32r(c.x); c.y = tf32r(c.y); c.z = tf32r(c.z); c.w = tf32r(c.w);
    ((float4*)g_w2r)[i] = c;
}

// ---------------------------------------------------------------------------
// 4) Gather selected tokens, RN-round to tf32
// ---------------------------------------------------------------------------
__global__ void k_gather(const float* __restrict__ x) {
    const int row = blockIdx.x;
    const int pair = row >> 9, b = pair >> 3;
    const int tok = g_idx[pair * TOPK + (row & 511)];
    const float4* src = (const float4*)(x + ((size_t)b * SEQ + tok) * DM);
    float4* dst = (float4*)(g_xg + (size_t)row * DM);
    for (int i = threadIdx.x; i < DM / 4; i += 128) {
        float4 v = src[i];
        v.x = tf32r(v.x); v.y = tf32r(v.y); v.z = tf32r(v.z); v.w = tf32r(v.w);
        dst[i] = v;
    }
}

// ---------------------------------------------------------------------------
// 5) tf32 mma.sync GEMM. CTA tile 128x128, 8 warps (4x2), warp tile 32x64,
//    K-slab 32, double-buffered cp.async. Smem rows stride 36 words
//    (conflict-free for the m16n8k8 fragment pattern, 16B-aligned).
// ---------------------------------------------------------------------------
#define SROW      36
#define AB_WORDS  (128 * SROW)           // 4608 words per matrix
#define STAGE_W   (2 * AB_WORDS)         // 9216 words per stage
#define SMEM_MMA  (2 * STAGE_W * 4)      // 73728 bytes

template<int K, bool G1>
__global__ void __launch_bounds__(256, 2) k_mma(const float* __restrict__ Aall,
                                                const float* __restrict__ Ball,
                                                float* __restrict__ out) {
    constexpr int NS = K / 32;
    extern __shared__ __align__(16) float smemf[];
    const uint32_t sb = smem_u32(smemf);

    const int tid  = threadIdx.x;
    const int wid  = tid >> 5, lane = tid & 31;
    const int wm   = wid >> 1, wn = wid & 1;
    const int g    = lane >> 2, tg = lane & 3;

    const int pair  = blockIdx.z, e = pair & 7, b = pair >> 3;
    const int mBase = blockIdx.y * 128;
    const int nBase = blockIdx.x * 128;

    const float* Abase = Aall + ((size_t)pair * TOPK + mBase) * K;
    const float* Bbase = Ball + (size_t)e * DF * DM + (size_t)nBase * K;

    auto load_slab = [&](int slab, int buf) {
        const float* Ap = Abase + slab * 32;
        const float* Bp = Bbase + slab * 32;
        const uint32_t sA = sb + buf * (STAGE_W * 4);
        const uint32_t sB = sA + AB_WORDS * 4;
#pragma unroll
        for (int i = 0; i < 4; i++) {
            const int ch = tid + i * 256;          // 0..1023
            const int row = ch >> 3, c16 = ch & 7;
            const uint32_t off = (row * SROW + c16 * 4) * 4;
            CP16(sA + off, Ap + (size_t)row * K + c16 * 4);
            CP16(sB + off, Bp + (size_t)row * K + c16 * 4);
        }
    };

    float acc[2][8][4];
#pragma unroll
    for (int mt = 0; mt < 2; mt++)
#pragma unroll
        for (int nt = 0; nt < 8; nt++)
#pragma unroll
            for (int f = 0; f < 4; f++) acc[mt][nt][f] = 0.f;

    load_slab(0, 0); CP_COMMIT();

#pragma unroll 1
    for (int s = 0; s < NS; s++) {
        if (s + 1 < NS) {
            load_slab(s + 1, (s + 1) & 1); CP_COMMIT();
            asm volatile("cp.async.wait_group 1;" ::: "memory");
        } else {
            asm volatile("cp.async.wait_group 0;" ::: "memory");
        }
        __syncthreads();

        const float* As = smemf + (s & 1) * STAGE_W;
        const float* Bs = As + AB_WORDS;
#pragma unroll
        for (int k = 0; k < 4; k++) {
            const int c = k * 8 + tg;
            uint32_t afr[2][4];
#pragma unroll
            for (int mt = 0; mt < 2; mt++) {
                const int r = wm * 32 + mt * 16 + g;
                afr[mt][0] = __float_as_uint(As[r * SROW + c]);
                afr[mt][1] = __float_as_uint(As[(r + 8) * SROW + c]);
                afr[mt][2] = __float_as_uint(As[r * SROW + c + 4]);
                afr[mt][3] = __float_as_uint(As[(r + 8) * SROW + c + 4]);
            }
            uint32_t bfr[8][2];
#pragma unroll
            for (int nt = 0; nt < 8; nt++) {
                const int rn = wn * 64 + nt * 8 + g;
                bfr[nt][0] = __float_as_uint(Bs[rn * SROW + c]);
                bfr[nt][1] = __float_as_uint(Bs[rn * SROW + c + 4]);
            }
#pragma unroll
            for (int mt = 0; mt < 2; mt++)
#pragma unroll
                for (int nt = 0; nt < 8; nt++)
                    mma_tf32(acc[mt][nt], afr[mt], bfr[nt]);
        }
        __syncthreads();
    }

    // ---- epilogue ----
    if (G1) {
#pragma unroll
        for (int mt = 0; mt < 2; mt++) {
            const int r0 = mBase + wm * 32 + mt * 16 + g;
#pragma unroll
            for (int nt = 0; nt < 8; nt++) {
                const int col = nBase + wn * 64 + nt * 8 + 2 * tg;
                const float* a = acc[mt][nt];
                float2 lo, hi;
                lo.x = tf32r(a[0] / (1.f + __expf(-a[0])));
                lo.y = tf32r(a[1] / (1.f + __expf(-a[1])));
                hi.x = tf32r(a[2] / (1.f + __expf(-a[2])));
                hi.y = tf32r(a[3] / (1.f + __expf(-a[3])));
                *(float2*)(out + ((size_t)pair * TOPK + r0) * DF + col)       = lo;
                *(float2*)(out + ((size_t)pair * TOPK + r0 + 8) * DF + col)   = hi;
            }
        }
    } else {
#pragma unroll
        for (int mt = 0; mt < 2; mt++) {
            const int m0 = mBase + wm * 32 + mt * 16 + g;
            const int tok0 = g_idx[pair * TOPK + m0];
            const int tok1 = g_idx[pair * TOPK + m0 + 8];
            const float g0 = g_gate[pair * TOPK + m0];
            const float g1 = g_gate[pair * TOPK + m0 + 8];
            float* d0 = out + ((size_t)b * SEQ + tok0) * DM;
            float* d1 = out + ((size_t)b * SEQ + tok1) * DM;
#pragma unroll
            for (int nt = 0; nt < 8; nt++) {
                const int col = nBase + wn * 64 + nt * 8 + 2 * tg;
                const float* a = acc[mt][nt];
                atomicAdd(d0 + col,     g0 * a[0]);
                atomicAdd(d0 + col + 1, g0 * a[1]);
                atomicAdd(d1 + col,     g1 * a[2]);
                atomicAdd(d1 + col + 1, g1 * a[3]);
            }
        }
    }
}

// ---------------------------------------------------------------------------
// 6) Zero output (poisoned before timing)
// ---------------------------------------------------------------------------
__global__ void k_zero(float* __restrict__ out, int n4) {
    const int i = blockIdx.x * blockDim.x + threadIdx.x;
    if (i < n4) ((float4*)out)[i] = make_float4(0.f, 0.f, 0.f, 0.f);
}

// ---------------------------------------------------------------------------
extern "C" void kernel_launch(void* const* d_in, const int* in_sizes, int n_in,
                              void* d_out, int out_size) {
    const float* x      = (const float*)d_in[0];
    const float* choice = (const float*)d_in[1];
    const float* w1     = (const float*)d_in[2];
    const float* w2     = (const float*)d_in[3];
    float* out = (float*)d_out;

    static int inited = 0;
    if (!inited) {
        cudaFuncSetAttribute(k_mma<DM, true>,  cudaFuncAttributeMaxDynamicSharedMemorySize, SMEM_MMA);
        cudaFuncSetAttribute(k_mma<DF, false>, cudaFuncAttributeMaxDynamicSharedMemorySize, SMEM_MMA);
        inited = 1;
    }

    float* xg_p;  cudaGetSymbolAddress((void**)&xg_p,  g_xg);
    float* h_p;   cudaGetSymbolAddress((void**)&h_p,   g_h);
    float* w1r_p; cudaGetSymbolAddress((void**)&w1r_p, g_w1r);
    float* w2r_p; cudaGetSymbolAddress((void**)&w2r_p, g_w2r);

    k_route<<<BATCH * SEQ, 128>>>(x, choice);
    k_topk<<<NPAIR, 1024>>>();

    const size_t N4 = (size_t)NE * DF * DM / 4;
    k_prep<<<(unsigned)((N4 + 255) / 256), 256>>>(w1, w2);
    k_gather<<<NPAIR * TOPK, 128>>>(x);

    // GEMM1: [512 x 4096], K=1024 per pair
    k_mma<DM, true><<<dim3(DF / 128, TOPK / 128, NPAIR), 256, SMEM_MMA>>>(xg_p, w1r_p, h_p);

    const int n4 = BATCH * SEQ * DM / 4;
    k_zero<<<(n4 + 255) / 256, 256>>>(out, n4);

    // GEMM2: [512 x 1024], K=4096 per pair
    k_mma<DF, false><<<dim3(DM / 128, TOPK / 128, NPAIR), 256, SMEM_MMA>>>(h_p, w2r_p, out);
}

// round 4
// speedup vs baseline: 5.9618x; 1.6727x over previous
#include <cuda_runtime.h>
#include <cuda_fp16.h>
#include <cstdint>
#include <math.h>

// ---------------------------------------------------------------------------
// MoE expert-choice via mma.sync fp16 (f32 accum). sm_103 ptxas lacks tcgen05.
// route -> top-512/expert -> gather(fp16) -> GEMM1+SiLU -> GEMM2 -> scatter
// ---------------------------------------------------------------------------

#define NE     8
#define DM     1024
#define DF     4096
#define SEQ    2048
#define BATCH  4
#define TOPK   512
#define NPAIR  32

__device__ float  g_probs[BATCH * SEQ * NE];
__device__ int    g_idx[NPAIR * TOPK];
__device__ float  g_gate[NPAIR * TOPK];
__device__ __align__(128) __half g_xg16[(size_t)NPAIR * TOPK * DM];   //  33MB
__device__ __align__(128) __half g_h16 [(size_t)NPAIR * TOPK * DF];   // 134MB
__device__ __align__(128) __half g_w1h [(size_t)NE * DF * DM];        //  67MB
__device__ __align__(128) __half g_w2h [(size_t)NE * DM * DF];        //  67MB

#define CP16(dst, src)  asm volatile("cp.async.cg.shared.global [%0], [%1], 16;" :: "r"(dst), "l"(src))
#define CP_COMMIT()     asm volatile("cp.async.commit_group;" ::: "memory")

__device__ __forceinline__ uint32_t smem_u32(const void* p) {
    uint32_t a;
    asm("{ .reg .u64 t; cvta.to.shared.u64 t, %1; cvt.u32.u64 %0, t; }" : "=r"(a) : "l"(p));
    return a;
}

#define LDSM4(r0, r1, r2, r3, addr) \
    asm volatile("ldmatrix.sync.aligned.m8n8.x4.shared.b16 {%0,%1,%2,%3}, [%4];" \
        : "=r"(r0), "=r"(r1), "=r"(r2), "=r"(r3) : "r"(addr))

__device__ __forceinline__ void mma_f16(float* c, const uint32_t* a, const uint32_t* b) {
    asm volatile(
        "mma.sync.aligned.m16n8k16.row.col.f32.f16.f16.f32 "
        "{%0,%1,%2,%3}, {%4,%5,%6,%7}, {%8,%9}, {%0,%1,%2,%3};"
        : "+f"(c[0]), "+f"(c[1]), "+f"(c[2]), "+f"(c[3])
        : "r"(a[0]), "r"(a[1]), "r"(a[2]), "r"(a[3]), "r"(b[0]), "r"(b[1]));
}

// ---------------------------------------------------------------------------
// 1) Routing softmax (fp32 exact — selection must match reference)
// ---------------------------------------------------------------------------
__global__ void k_route(const float* __restrict__ x, const float* __restrict__ choice) {
    const int token = blockIdx.x;
    const float* xr = x + (size_t)token * DM;
    const int t = threadIdx.x;               // 128

    float acc[NE];
#pragma unroll
    for (int e = 0; e < NE; e++) acc[e] = 0.f;
    for (int d = t; d < DM; d += 128) {
        const float xv = xr[d];
#pragma unroll
        for (int e = 0; e < NE; e++) acc[e] = fmaf(xv, choice[e * DM + d], acc[e]);
    }
    __shared__ float red[NE][128];
#pragma unroll
    for (int e = 0; e < NE; e++) red[e][t] = acc[e];
    __syncthreads();
    for (int ofs = 64; ofs > 0; ofs >>= 1) {
        if (t < ofs) {
#pragma unroll
            for (int e = 0; e < NE; e++) red[e][t] += red[e][t + ofs];
        }
        __syncthreads();
    }
    if (t == 0) {
        float l[NE], mx = -1e30f;
#pragma unroll
        for (int e = 0; e < NE; e++) { l[e] = red[e][0]; mx = fmaxf(mx, l[e]); }
        float s = 0.f;
#pragma unroll
        for (int e = 0; e < NE; e++) { l[e] = expf(l[e] - mx); s += l[e]; }
        const float inv = 1.f / s;
#pragma unroll
        for (int e = 0; e < NE; e++) g_probs[token * NE + e] = l[e] * inv;
    }
}

// ---------------------------------------------------------------------------
// 2) Exact top-K per (batch, expert)
// ---------------------------------------------------------------------------
__global__ void k_topk() {
    const int pair = blockIdx.x, b = pair >> 3, e = pair & 7;
    const int t = threadIdx.x;               // 1024
    __shared__ unsigned keys[SEQ];
    __shared__ int s_cnt;

    for (int s = t; s < SEQ; s += blockDim.x) {
        unsigned bits = __float_as_uint(g_probs[((size_t)b * SEQ + s) * NE + e]);
        keys[s] = (bits & 0x80000000u) ? ~bits : (bits | 0x80000000u);
    }
    __syncthreads();

    unsigned lo = 0u, hi = 0xFFFFFFFFu;
    while (lo < hi) {
        const unsigned mid = lo + ((hi - lo) >> 1) + 1u;
        if (t == 0) s_cnt = 0;
        __syncthreads();
        int c = 0;
        for (int s = t; s < SEQ; s += blockDim.x) c += (keys[s] >= mid);
#pragma unroll
        for (int o = 16; o > 0; o >>= 1) c += __shfl_down_sync(0xffffffffu, c, o);
        if ((t & 31) == 0 && c) atomicAdd(&s_cnt, c);
        __syncthreads();
        const int cnt = s_cnt;
        __syncthreads();
        if (cnt >= TOPK) lo = mid; else hi = mid - 1u;
    }
    const unsigned T = lo;

    if (t == 0) s_cnt = 0;
    __syncthreads();
    for (int s = t; s < SEQ; s += blockDim.x) {
        if (keys[s] > T) {
            const int p = atomicAdd(&s_cnt, 1);
            g_idx[pair * TOPK + p]  = s;
            g_gate[pair * TOPK + p] = g_probs[((size_t)b * SEQ + s) * NE + e];
        }
    }
    __syncthreads();
    for (int s = t; s < SEQ; s += blockDim.x) {
        if (keys[s] == T) {
            const int p = atomicAdd(&s_cnt, 1);
            if (p < TOPK) {
                g_idx[pair * TOPK + p]  = s;
                g_gate[pair * TOPK + p] = g_probs[((size_t)b * SEQ + s) * NE + e];
            }
        }
    }
}

// ---------------------------------------------------------------------------
// 3) Weight prep: RN-round fp32 -> fp16
// ---------------------------------------------------------------------------
__global__ void k_prep(const float* __restrict__ w1, const float* __restrict__ w2) {
    const size_t i = (size_t)blockIdx.x * blockDim.x + threadIdx.x;   // float4 idx
    const size_t N4 = (size_t)NE * DF * DM / 4;
    if (i >= N4) return;
    float4 a = ((const float4*)w1)[i];
    __half2 a0 = __floats2half2_rn(a.x, a.y);
    __half2 a1 = __floats2half2_rn(a.z, a.w);
    uint2 ua;
    ua.x = *reinterpret_cast<unsigned*>(&a0);
    ua.y = *reinterpret_cast<unsigned*>(&a1);
    ((uint2*)g_w1h)[i] = ua;
    float4 c = ((const float4*)w2)[i];
    __half2 c0 = __floats2half2_rn(c.x, c.y);
    __half2 c1 = __floats2half2_rn(c.z, c.w);
    uint2 uc;
    uc.x = *reinterpret_cast<unsigned*>(&c0);
    uc.y = *reinterpret_cast<unsigned*>(&c1);
    ((uint2*)g_w2h)[i] = uc;
}

// ---------------------------------------------------------------------------
// 4) Gather selected tokens, fp32 -> fp16
// ---------------------------------------------------------------------------
__global__ void k_gather(const float* __restrict__ x) {
    const int row = blockIdx.x;
    const int pair = row >> 9, b = pair >> 3;
    const int tok = g_idx[pair * TOPK + (row & 511)];
    const float4* src = (const float4*)(x + ((size_t)b * SEQ + tok) * DM);
    uint2* dst = (uint2*)(g_xg16 + (size_t)row * DM);
    for (int i = threadIdx.x; i < DM / 4; i += 128) {
        float4 v = src[i];
        __half2 h0 = __floats2half2_rn(v.x, v.y);
        __half2 h1 = __floats2half2_rn(v.z, v.w);
        uint2 u;
        u.x = *reinterpret_cast<unsigned*>(&h0);
        u.y = *reinterpret_cast<unsigned*>(&h1);
        dst[i] = u;
    }
}

// ---------------------------------------------------------------------------
// 5) fp16 mma.sync GEMM. CTA tile 128x128, 8 warps (4x2), warp tile 32x64,
//    K-slab 32 halves, double-buffered cp.async, ldmatrix fragment loads.
//    Smem rows padded to 40 halves (80B): bank starts {0,20,8,28,16,4,24,12}
//    -> conflict-free ldmatrix.
// ---------------------------------------------------------------------------
#define SPAD        40
#define A_BYTES     (128 * SPAD * 2)     // 10240
#define STAGE_BYTES (2 * A_BYTES)        // 20480
#define SMEM_MMA    (2 * STAGE_BYTES)    // 40960

template<int K, bool G1>
__global__ void __launch_bounds__(256, 2) k_mma(const __half* __restrict__ Aall,
                                                const __half* __restrict__ Ball,
                                                void* __restrict__ outp) {
    constexpr int NS = K / 32;
    __shared__ __align__(16) char smem[SMEM_MMA];
    const uint32_t sb = smem_u32(smem);

    const int tid  = threadIdx.x;
    const int wid  = tid >> 5, lane = tid & 31;
    const int wm   = wid >> 1, wn = wid & 1;
    const int g    = lane >> 2, tg = lane & 3;
    const int mi   = lane >> 3, r8 = lane & 7;

    const int pair  = blockIdx.z, e = pair & 7, b = pair >> 3;
    const int mBase = blockIdx.y * 128;
    const int nBase = blockIdx.x * 128;

    const __half* Abase = Aall + ((size_t)pair * TOPK + mBase) * K;
    const __half* Bbase = Ball + (size_t)e * DF * DM + (size_t)nBase * K;

    // ldmatrix per-thread relative byte offsets
    uint32_t aoff[2], boff[4];
#pragma unroll
    for (int mt = 0; mt < 2; mt++)
        aoff[mt] = ((wm * 32 + mt * 16 + (mi & 1) * 8 + r8) * SPAD + (mi >> 1) * 8) * 2;
#pragma unroll
    for (int np = 0; np < 4; np++)
        boff[np] = ((wn * 64 + np * 16 + (mi >> 1) * 8 + r8) * SPAD + (mi & 1) * 8) * 2;

    auto load_slab = [&](int slab, int buf) {
        const char* Ap = (const char*)(Abase) + (size_t)slab * 64;
        const char* Bp = (const char*)(Bbase) + (size_t)slab * 64;
        const uint32_t sA = sb + buf * STAGE_BYTES;
        const uint32_t sB = sA + A_BYTES;
#pragma unroll
        for (int i = 0; i < 2; i++) {
            const int id = tid + i * 256;        // 0..511
            const int row = id >> 2, c16 = id & 3;
            const uint32_t off = row * (SPAD * 2) + c16 * 16;
            CP16(sA + off, Ap + (size_t)row * (K * 2) + c16 * 16);
            CP16(sB + off, Bp + (size_t)row * (K * 2) + c16 * 16);
        }
    };

    float acc[2][8][4];
#pragma unroll
    for (int mt = 0; mt < 2; mt++)
#pragma unroll
        for (int nt = 0; nt < 8; nt++)
#pragma unroll
            for (int f = 0; f < 4; f++) acc[mt][nt][f] = 0.f;

    load_slab(0, 0); CP_COMMIT();

#pragma unroll 1
    for (int s = 0; s < NS; s++) {
        if (s + 1 < NS) {
            load_slab(s + 1, (s + 1) & 1); CP_COMMIT();
            asm volatile("cp.async.wait_group 1;" ::: "memory");
        } else {
            asm volatile("cp.async.wait_group 0;" ::: "memory");
        }
        __syncthreads();

        const uint32_t sA = sb + (s & 1) * STAGE_BYTES;
        const uint32_t sB = sA + A_BYTES;
#pragma unroll
        for (int ks = 0; ks < 2; ks++) {
            const uint32_t kofs = ks * 32;       // 16 halves
            uint32_t af[2][4];
#pragma unroll
            for (int mt = 0; mt < 2; mt++)
                LDSM4(af[mt][0], af[mt][1], af[mt][2], af[mt][3], sA + aoff[mt] + kofs);
            uint32_t bf[8][2];
#pragma unroll
            for (int np = 0; np < 4; np++)
                LDSM4(bf[2 * np][0], bf[2 * np][1], bf[2 * np + 1][0], bf[2 * np + 1][1],
                      sB + boff[np] + kofs);
#pragma unroll
            for (int mt = 0; mt < 2; mt++)
#pragma unroll
                for (int nt = 0; nt < 8; nt++)
                    mma_f16(acc[mt][nt], af[mt], bf[nt]);
        }
        __syncthreads();
    }

    // ---- epilogue ----
    if (G1) {
        __half* hout = (__half*)outp;
#pragma unroll
        for (int mt = 0; mt < 2; mt++) {
            const int r0 = mBase + wm * 32 + mt * 16 + g;
#pragma unroll
            for (int nt = 0; nt < 8; nt++) {
                const int col = nBase + wn * 64 + nt * 8 + 2 * tg;
                const float* a = acc[mt][nt];
                __half2 lo = __floats2half2_rn(a[0] / (1.f + __expf(-a[0])),
                                               a[1] / (1.f + __expf(-a[1])));
                __half2 hi = __floats2half2_rn(a[2] / (1.f + __expf(-a[2])),
                                               a[3] / (1.f + __expf(-a[3])));
                *(unsigned*)(hout + ((size_t)pair * TOPK + r0) * DF + col)     = *reinterpret_cast<unsigned*>(&lo);
                *(unsigned*)(hout + ((size_t)pair * TOPK + r0 + 8) * DF + col) = *reinterpret_cast<unsigned*>(&hi);
            }
        }
    } else {
        float* out = (float*)outp;
#pragma unroll
        for (int mt = 0; mt < 2; mt++) {
            const int m0 = mBase + wm * 32 + mt * 16 + g;
            const int tok0 = g_idx[pair * TOPK + m0];
            const int tok1 = g_idx[pair * TOPK + m0 + 8];
            const float g0 = g_gate[pair * TOPK + m0];
            const float g1 = g_gate[pair * TOPK + m0 + 8];
            float* d0 = out + ((size_t)b * SEQ + tok0) * DM;
            float* d1 = out + ((size_t)b * SEQ + tok1) * DM;
#pragma unroll
            for (int nt = 0; nt < 8; nt++) {
                const int col = nBase + wn * 64 + nt * 8 + 2 * tg;
                const float* a = acc[mt][nt];
                atomicAdd(d0 + col,     g0 * a[0]);
                atomicAdd(d0 + col + 1, g0 * a[1]);
                atomicAdd(d1 + col,     g1 * a[2]);
                atomicAdd(d1 + col + 1, g1 * a[3]);
            }
        }
    }
}

// ---------------------------------------------------------------------------
// 6) Zero output (poisoned before timing)
// ---------------------------------------------------------------------------
__global__ void k_zero(float* __restrict__ out, int n4) {
    const int i = blockIdx.x * blockDim.x + threadIdx.x;
    if (i < n4) ((float4*)out)[i] = make_float4(0.f, 0.f, 0.f, 0.f);
}

// ---------------------------------------------------------------------------
extern "C" void kernel_launch(void* const* d_in, const int* in_sizes, int n_in,
                              void* d_out, int out_size) {
    const float* x      = (const float*)d_in[0];
    const float* choice = (const float*)d_in[1];
    const float* w1     = (const float*)d_in[2];
    const float* w2     = (const float*)d_in[3];
    float* out = (float*)d_out;

    __half* xg_p;  cudaGetSymbolAddress((void**)&xg_p,  g_xg16);
    __half* h_p;   cudaGetSymbolAddress((void**)&h_p,   g_h16);
    __half* w1h_p; cudaGetSymbolAddress((void**)&w1h_p, g_w1h);
    __half* w2h_p; cudaGetSymbolAddress((void**)&w2h_p, g_w2h);

    k_route<<<BATCH * SEQ, 128>>>(x, choice);
    k_topk<<<NPAIR, 1024>>>();

    const size_t N4 = (size_t)NE * DF * DM / 4;
    k_prep<<<(unsigned)((N4 + 255) / 256), 256>>>(w1, w2);
    k_gather<<<NPAIR * TOPK, 128>>>(x);

    // GEMM1: [512 x 4096], K=1024 per pair
    k_mma<DM, true><<<dim3(DF / 128, TOPK / 128, NPAIR), 256>>>(xg_p, w1h_p, h_p);

    const int n4 = BATCH * SEQ * DM / 4;
    k_zero<<<(n4 + 255) / 256, 256>>>(out, n4);

    // GEMM2: [512 x 1024], K=4096 per pair
    k_mma<DF, false><<<dim3(DM / 128, TOPK / 128, NPAIR), 256>>>(h_p, w2h_p, out);
}